// round 1
// baseline (speedup 1.0000x reference)
#include <cuda_runtime.h>
#include <cuda_bf16.h>
#include <cstdint>

// Problem constants
#define BSZ 16384
#define EDIM 1024
#define TDIM 768
#define ADIM 1024

// Scratch (allocation-free rule: __device__ globals)
__device__ float g_t[(size_t)BSZ * EDIM];
__device__ float g_a[(size_t)BSZ * EDIM];
__device__ float g_tctx[(size_t)BSZ * EDIM];
__device__ float g_actx[(size_t)BSZ * EDIM];
__device__ float g_WvT[(size_t)EDIM * EDIM];
__device__ float g_Wvo[(size_t)EDIM * EDIM];
__device__ float g_bvo[EDIM];

#define BM 128
#define BN 128
#define BK 8

// C[M,N] = A[M,K] @ W[N,K]^T (+ bias[N]); all row-major, K-contiguous operands.
__global__ __launch_bounds__(256) void sgemm_nt(
    const float* __restrict__ A, const float* __restrict__ W,
    const float* __restrict__ bias, float* __restrict__ C,
    int M, int N, int K)
{
    __shared__ float As[BK][BM];
    __shared__ float Bs[BK][BN];
    const int tid = threadIdx.x;
    const int bm = blockIdx.y * BM;
    const int bn = blockIdx.x * BN;
    const int tx = tid & 15;   // column group
    const int ty = tid >> 4;   // row group
    const int lrow = tid >> 1;         // 0..127
    const int lcol = (tid & 1) * 4;    // 0 or 4

    const float* Aptr = A + (size_t)(bm + lrow) * K + lcol;
    const float* Wptr = W + (size_t)(bn + lrow) * K + lcol;

    float acc[8][8];
#pragma unroll
    for (int i = 0; i < 8; i++)
#pragma unroll
        for (int j = 0; j < 8; j++) acc[i][j] = 0.f;

    for (int k0 = 0; k0 < K; k0 += BK) {
        float4 av = *reinterpret_cast<const float4*>(Aptr + k0);
        float4 wv = *reinterpret_cast<const float4*>(Wptr + k0);
        As[lcol + 0][lrow] = av.x; As[lcol + 1][lrow] = av.y;
        As[lcol + 2][lrow] = av.z; As[lcol + 3][lrow] = av.w;
        Bs[lcol + 0][lrow] = wv.x; Bs[lcol + 1][lrow] = wv.y;
        Bs[lcol + 2][lrow] = wv.z; Bs[lcol + 3][lrow] = wv.w;
        __syncthreads();
#pragma unroll
        for (int k = 0; k < BK; k++) {
            float ar[8], br[8];
            *(float4*)&ar[0] = *(const float4*)&As[k][ty * 4];
            *(float4*)&ar[4] = *(const float4*)&As[k][64 + ty * 4];
            *(float4*)&br[0] = *(const float4*)&Bs[k][tx * 4];
            *(float4*)&br[4] = *(const float4*)&Bs[k][64 + tx * 4];
#pragma unroll
            for (int i = 0; i < 8; i++)
#pragma unroll
                for (int j = 0; j < 8; j++)
                    acc[i][j] = fmaf(ar[i], br[j], acc[i][j]);
        }
        __syncthreads();
    }

#pragma unroll
    for (int ih = 0; ih < 2; ih++)
#pragma unroll
        for (int i = 0; i < 4; i++) {
            const int row = bm + ih * 64 + ty * 4 + i;
#pragma unroll
            for (int jh = 0; jh < 2; jh++) {
                const int col = bn + jh * 64 + tx * 4;
                float4 v;
                v.x = acc[ih * 4 + i][jh * 4 + 0];
                v.y = acc[ih * 4 + i][jh * 4 + 1];
                v.z = acc[ih * 4 + i][jh * 4 + 2];
                v.w = acc[ih * 4 + i][jh * 4 + 3];
                if (bias) {
                    v.x += bias[col + 0]; v.y += bias[col + 1];
                    v.z += bias[col + 2]; v.w += bias[col + 3];
                }
                *reinterpret_cast<float4*>(C + (size_t)row * N + col) = v;
            }
        }
}

// Fused gate: pre = X@Wg[:, :E]^T + Xc@Wg[:, E:]^T + bg; g = sigmoid(pre);
// Out = g*X + (1-g)*Xc.   X, Xc, Out are (BSZ, EDIM); Wg is (EDIM, 2*EDIM).
__global__ __launch_bounds__(256) void gate_gemm(
    const float* __restrict__ X, const float* __restrict__ Xc,
    const float* __restrict__ Wg, const float* __restrict__ bg,
    float* __restrict__ Out)
{
    __shared__ float As[BK][BM];
    __shared__ float Bs[BK][BN];
    const int tid = threadIdx.x;
    const int bm = blockIdx.y * BM;
    const int bn = blockIdx.x * BN;
    const int tx = tid & 15;
    const int ty = tid >> 4;
    const int lrow = tid >> 1;
    const int lcol = (tid & 1) * 4;

    float acc[8][8];
#pragma unroll
    for (int i = 0; i < 8; i++)
#pragma unroll
        for (int j = 0; j < 8; j++) acc[i][j] = 0.f;

    const float* Wbase = Wg + (size_t)(bn + lrow) * (2 * EDIM) + lcol;

    for (int ph = 0; ph < 2; ph++) {
        const float* Ap = (ph == 0 ? X : Xc) + (size_t)(bm + lrow) * EDIM + lcol;
        const float* Wp = Wbase + ph * EDIM;
        for (int k0 = 0; k0 < EDIM; k0 += BK) {
            float4 av = *reinterpret_cast<const float4*>(Ap + k0);
            float4 wv = *reinterpret_cast<const float4*>(Wp + k0);
            As[lcol + 0][lrow] = av.x; As[lcol + 1][lrow] = av.y;
            As[lcol + 2][lrow] = av.z; As[lcol + 3][lrow] = av.w;
            Bs[lcol + 0][lrow] = wv.x; Bs[lcol + 1][lrow] = wv.y;
            Bs[lcol + 2][lrow] = wv.z; Bs[lcol + 3][lrow] = wv.w;
            __syncthreads();
#pragma unroll
            for (int k = 0; k < BK; k++) {
                float ar[8], br[8];
                *(float4*)&ar[0] = *(const float4*)&As[k][ty * 4];
                *(float4*)&ar[4] = *(const float4*)&As[k][64 + ty * 4];
                *(float4*)&br[0] = *(const float4*)&Bs[k][tx * 4];
                *(float4*)&br[4] = *(const float4*)&Bs[k][64 + tx * 4];
#pragma unroll
                for (int i = 0; i < 8; i++)
#pragma unroll
                    for (int j = 0; j < 8; j++)
                        acc[i][j] = fmaf(ar[i], br[j], acc[i][j]);
            }
            __syncthreads();
        }
    }

#pragma unroll
    for (int ih = 0; ih < 2; ih++)
#pragma unroll
        for (int i = 0; i < 4; i++) {
            const int row = bm + ih * 64 + ty * 4 + i;
#pragma unroll
            for (int jh = 0; jh < 2; jh++) {
                const int col = bn + jh * 64 + tx * 4;
                const size_t off = (size_t)row * EDIM + col;
                float4 xv = *reinterpret_cast<const float4*>(X + off);
                float4 cv = *reinterpret_cast<const float4*>(Xc + off);
                float pre[4];
                pre[0] = acc[ih * 4 + i][jh * 4 + 0] + bg[col + 0];
                pre[1] = acc[ih * 4 + i][jh * 4 + 1] + bg[col + 1];
                pre[2] = acc[ih * 4 + i][jh * 4 + 2] + bg[col + 2];
                pre[3] = acc[ih * 4 + i][jh * 4 + 3] + bg[col + 3];
                float4 o;
                {
                    float gx = 1.f / (1.f + __expf(-pre[0]));
                    o.x = gx * xv.x + (1.f - gx) * cv.x;
                    float gy = 1.f / (1.f + __expf(-pre[1]));
                    o.y = gy * xv.y + (1.f - gy) * cv.y;
                    float gz = 1.f / (1.f + __expf(-pre[2]));
                    o.z = gz * xv.z + (1.f - gz) * cv.z;
                    float gw = 1.f / (1.f + __expf(-pre[3]));
                    o.w = gw * xv.w + (1.f - gw) * cv.w;
                }
                *reinterpret_cast<float4*>(Out + off) = o;
            }
        }
}

// 1024x1024 transpose: out[k][j] = in[j][k]
__global__ void transpose1024(const float* __restrict__ in, float* __restrict__ out)
{
    __shared__ float tile[32][33];
    int x = blockIdx.x * 32 + threadIdx.x;
    int y = blockIdx.y * 32 + threadIdx.y;
#pragma unroll
    for (int i = 0; i < 32; i += 8)
        tile[threadIdx.y + i][threadIdx.x] = in[(size_t)(y + i) * EDIM + x];
    __syncthreads();
    x = blockIdx.y * 32 + threadIdx.x;
    y = blockIdx.x * 32 + threadIdx.y;
#pragma unroll
    for (int i = 0; i < 32; i += 8)
        out[(size_t)(y + i) * EDIM + x] = tile[threadIdx.x][threadIdx.y + i];
}

// bvo[n] = Wo[n,:] . bv + bo[n]   (one warp per n)
__global__ void bvo_kernel(const float* __restrict__ Wo, const float* __restrict__ bv,
                           const float* __restrict__ bo, float* __restrict__ bvo)
{
    int n = blockIdx.x * (blockDim.x >> 5) + (threadIdx.x >> 5);
    int lane = threadIdx.x & 31;
    const float* row = Wo + (size_t)n * EDIM;
    float s = 0.f;
    for (int k = lane; k < EDIM; k += 32) s += row[k] * bv[k];
#pragma unroll
    for (int off = 16; off; off >>= 1) s += __shfl_xor_sync(0xFFFFFFFFu, s, off);
    if (lane == 0) bvo[n] = s + bo[n];
}

extern "C" void kernel_launch(void* const* d_in, const int* in_sizes, int n_in,
                              void* d_out, int out_size)
{
    const float* text  = (const float*)d_in[0];
    const float* audio = (const float*)d_in[1];
    const float* Wt  = (const float*)d_in[2];
    const float* bt  = (const float*)d_in[3];
    const float* Wa  = (const float*)d_in[4];
    const float* ba  = (const float*)d_in[5];
    // d_in[6..9] = Wq,bq,Wk,bk : dead (softmax over a length-1 axis is identically 1)
    const float* Wv  = (const float*)d_in[10];
    const float* bv  = (const float*)d_in[11];
    const float* Wo  = (const float*)d_in[12];
    const float* bo  = (const float*)d_in[13];
    const float* Wgt = (const float*)d_in[14];
    const float* bgt = (const float*)d_in[15];
    const float* Wga = (const float*)d_in[16];
    const float* bga = (const float*)d_in[17];
    float* out = (float*)d_out;

    float *t, *a, *tctx, *actx, *WvT, *Wvo, *bvo;
    cudaGetSymbolAddress((void**)&t,    g_t);
    cudaGetSymbolAddress((void**)&a,    g_a);
    cudaGetSymbolAddress((void**)&tctx, g_tctx);
    cudaGetSymbolAddress((void**)&actx, g_actx);
    cudaGetSymbolAddress((void**)&WvT,  g_WvT);
    cudaGetSymbolAddress((void**)&Wvo,  g_Wvo);
    cudaGetSymbolAddress((void**)&bvo,  g_bvo);

    const dim3 blk(256);
    const dim3 gridBig(EDIM / BN, BSZ / BM);   // (8, 128)
    const dim3 gridW(EDIM / BN, EDIM / BM);    // (8, 8)

    // 1) WvT = Wv^T ; Wvo = Wo @ Wv  (as NT gemm: Wvo[n,k] = sum_j Wo[n,j]*WvT[k,j])
    transpose1024<<<dim3(32, 32), dim3(32, 8)>>>(Wv, WvT);
    sgemm_nt<<<gridW, blk>>>(Wo, WvT, nullptr, Wvo, EDIM, EDIM, EDIM);
    // 2) bvo = Wo @ bv + bo
    bvo_kernel<<<EDIM / 8, 256>>>(Wo, bv, bo, bvo);
    // 3) modality projections
    sgemm_nt<<<gridBig, blk>>>(text,  Wt, bt, t, BSZ, EDIM, TDIM);
    sgemm_nt<<<gridBig, blk>>>(audio, Wa, ba, a, BSZ, EDIM, ADIM);
    // 4) contexts (attention collapsed to V∘O projection)
    sgemm_nt<<<gridBig, blk>>>(a, Wvo, bvo, tctx, BSZ, EDIM, EDIM);
    sgemm_nt<<<gridBig, blk>>>(t, Wvo, bvo, actx, BSZ, EDIM, EDIM);
    // 5) fused gates + blend -> outputs
    gate_gemm<<<gridBig, blk>>>(t, tctx, Wgt, bgt, out);
    gate_gemm<<<gridBig, blk>>>(a, actx, Wga, bga, out + (size_t)BSZ * EDIM);
}

// round 3
// speedup vs baseline: 1.2160x; 1.2160x over previous
#include <cuda_runtime.h>
#include <cuda_bf16.h>
#include <mma.h>
#include <cstdint>

using namespace nvcuda;

#define BSZ 16384
#define EDIM 1024
#define TDIM 768

// ---------------- scratch (__device__ globals; allocation is forbidden) ----------------
__device__ float g_t[(size_t)BSZ * EDIM];      // rounded-to-tf32 fp32
__device__ float g_a[(size_t)BSZ * EDIM];
__device__ float g_tctx[(size_t)BSZ * EDIM];
__device__ float g_actx[(size_t)BSZ * EDIM];
__device__ float g_text_r[(size_t)BSZ * TDIM];
__device__ float g_aud_r[(size_t)BSZ * EDIM];
__device__ float g_Wt_r[(size_t)EDIM * TDIM];
__device__ float g_Wa_r[(size_t)EDIM * EDIM];
__device__ float g_Wgt_r[(size_t)EDIM * 2 * EDIM];
__device__ float g_Wga_r[(size_t)EDIM * 2 * EDIM];
__device__ float g_Wo_r[(size_t)EDIM * EDIM];
__device__ float g_WvT_r[(size_t)EDIM * EDIM];
__device__ float g_Wvo[(size_t)EDIM * EDIM];
__device__ float g_bvo[EDIM];

// ---------------- helpers ----------------
static __device__ __forceinline__ float to_tf32(float x) {
    float r;
    asm("cvt.rna.tf32.f32 %0, %1;" : "=f"(r) : "f"(x));
    return r;
}
static __device__ __forceinline__ uint32_t s2u(const void* p) {
    uint32_t a;
    asm("{ .reg .u64 t; cvta.to.shared.u64 t, %1; cvt.u32.u64 %0, t; }" : "=r"(a) : "l"(p));
    return a;
}
static __device__ __forceinline__ void cpa16(uint32_t d, const void* s) {
    asm volatile("cp.async.cg.shared.global [%0], [%1], 16;" :: "r"(d), "l"(s));
}
static __device__ __forceinline__ void cpa_commit() { asm volatile("cp.async.commit_group;"); }

// ---------------- SMEM layout ----------------
// K-tile = 32 floats/row, stored with row stride 40 floats (160 B) for bank spread.
// A buf 128*160 = 20480 B; layout: [A0][B0][A1][B1] = 81920 B total.
// Epilogue reuses base as Cs: 128 x 132 floats = 67584 B.
#define SMEM_BYTES 81920
#define ABUF(b) ((b) * 40960)
#define BBUF(b) ((b) * 40960 + 20480)

// ---------------- TF32 WMMA GEMM ----------------
// C[row, col] = sum_k A[row, k] * W[col, k]  (+ bias[col]); A-operand switches from
// A0 to A1 at k = Ksplit (concat-free gate). All mma operands are pre-rounded tf32.
// GATE: fused sigmoid gate + blend epilogue. !GATE: epilogue emits tf32-rounded C.
template <bool GATE>
__global__ __launch_bounds__(128) void tc_wmma(
    const float* __restrict__ A0, const float* __restrict__ A1, int lda,
    const float* __restrict__ W, int ldw, int K, int Ksplit,
    const float* __restrict__ bias, float* __restrict__ C,
    const float* __restrict__ X, const float* __restrict__ Xc)
{
    extern __shared__ __align__(16) char smem[];
    const uint32_t sb = s2u(smem);
    const int tid = threadIdx.x;
    const int warp = tid >> 5;
    const int bm = blockIdx.y * 128;
    const int bn = blockIdx.x * 128;
    const int wm = (warp >> 1) * 64;   // warp tile 64x64, warp grid 2x2
    const int wn = (warp & 1) * 64;
    const int T = K / 32;

    wmma::fragment<wmma::accumulator, 16, 16, 8, float> acc[4][4];
#pragma unroll
    for (int i = 0; i < 4; i++)
#pragma unroll
        for (int j = 0; j < 4; j++) wmma::fill_fragment(acc[i][j], 0.0f);

    auto issue = [&](int ti, int buf) {
        const int k0 = ti * 32;
        const float* Ap;
        int kk;
        if (!GATE || k0 < Ksplit) { Ap = A0; kk = k0; }
        else                      { Ap = A1; kk = k0 - Ksplit; }
        const float* srcA = Ap + (size_t)(bm + tid) * lda + kk;
        const uint32_t dA = sb + ABUF(buf) + tid * 160;
#pragma unroll
        for (int j = 0; j < 8; j++) cpa16(dA + j * 16, srcA + j * 4);
        const float* srcB = W + (size_t)(bn + tid) * ldw + k0;
        const uint32_t dB = sb + BBUF(buf) + tid * 160;
#pragma unroll
        for (int j = 0; j < 8; j++) cpa16(dB + j * 16, srcB + j * 4);
        cpa_commit();
    };

    issue(0, 0);
    issue(1, 1);

    for (int ti = 0; ti < T; ti++) {
        const int buf = ti & 1;
        if (ti + 1 < T) asm volatile("cp.async.wait_group 1;");
        else            asm volatile("cp.async.wait_group 0;");
        __syncthreads();

        const float* As = (const float*)(smem + ABUF(buf));
        const float* Bs = (const float*)(smem + BBUF(buf));
#pragma unroll
        for (int kk = 0; kk < 4; kk++) {
            wmma::fragment<wmma::matrix_a, 16, 16, 8, wmma::precision::tf32, wmma::row_major> af[4];
#pragma unroll
            for (int mi = 0; mi < 4; mi++)
                wmma::load_matrix_sync(af[mi], As + (wm + mi * 16) * 40 + kk * 8, 40);
#pragma unroll
            for (int ni = 0; ni < 4; ni++) {
                wmma::fragment<wmma::matrix_b, 16, 16, 8, wmma::precision::tf32, wmma::col_major> bf;
                wmma::load_matrix_sync(bf, Bs + (wn + ni * 16) * 40 + kk * 8, 40);
#pragma unroll
                for (int mi = 0; mi < 4; mi++)
                    wmma::mma_sync(acc[mi][ni], af[mi], bf, acc[mi][ni]);
            }
        }
        __syncthreads();
        if (ti + 2 < T) issue(ti + 2, buf);
    }

    // ---- epilogue: stage accumulators through smem, fuse bias (+ gate blend)
    float* Cs = (float*)smem;
#pragma unroll
    for (int mi = 0; mi < 4; mi++)
#pragma unroll
        for (int ni = 0; ni < 4; ni++)
            wmma::store_matrix_sync(Cs + (wm + mi * 16) * 132 + wn + ni * 16,
                                    acc[mi][ni], 132, wmma::mem_row_major);
    __syncthreads();

    {
        const int r = tid;                    // one full row per thread
        const size_t rowoff = (size_t)(bm + r) * EDIM + bn;
#pragma unroll 8
        for (int q = 0; q < 32; q++) {
            float4 v = *(const float4*)(Cs + r * 132 + q * 4);
            if (bias) {
                float4 bb = *(const float4*)(bias + bn + q * 4);
                v.x += bb.x; v.y += bb.y; v.z += bb.z; v.w += bb.w;
            }
            if (GATE) {
                float4 xv = *(const float4*)(X + rowoff + q * 4);
                float4 cv = *(const float4*)(Xc + rowoff + q * 4);
                float g0 = 1.f / (1.f + __expf(-v.x));
                float g1 = 1.f / (1.f + __expf(-v.y));
                float g2 = 1.f / (1.f + __expf(-v.z));
                float g3 = 1.f / (1.f + __expf(-v.w));
                v.x = g0 * xv.x + (1.f - g0) * cv.x;
                v.y = g1 * xv.y + (1.f - g1) * cv.y;
                v.z = g2 * xv.z + (1.f - g2) * cv.z;
                v.w = g3 * xv.w + (1.f - g3) * cv.w;
            } else {
                // round so downstream GEMMs can consume without in-loop cvt
                v.x = to_tf32(v.x); v.y = to_tf32(v.y);
                v.z = to_tf32(v.z); v.w = to_tf32(v.w);
            }
            *(float4*)(C + rowoff + q * 4) = v;
        }
    }
}

// ---------------- small helper kernels ----------------
__global__ void round_tf32_kernel(const float* __restrict__ in, float* __restrict__ out, int n4) {
    int i = blockIdx.x * blockDim.x + threadIdx.x;
    if (i >= n4) return;
    float4 v = ((const float4*)in)[i];
    v.x = to_tf32(v.x); v.y = to_tf32(v.y); v.z = to_tf32(v.z); v.w = to_tf32(v.w);
    ((float4*)out)[i] = v;
}

// out[k][j] = round_tf32(in[j][k]) for 1024x1024
__global__ void transpose_round1024(const float* __restrict__ in, float* __restrict__ out) {
    __shared__ float tile[32][33];
    int x = blockIdx.x * 32 + threadIdx.x;
    int y = blockIdx.y * 32 + threadIdx.y;
#pragma unroll
    for (int i = 0; i < 32; i += 8)
        tile[threadIdx.y + i][threadIdx.x] = in[(size_t)(y + i) * EDIM + x];
    __syncthreads();
    x = blockIdx.y * 32 + threadIdx.x;
    y = blockIdx.x * 32 + threadIdx.y;
#pragma unroll
    for (int i = 0; i < 32; i += 8)
        out[(size_t)(y + i) * EDIM + x] = to_tf32(tile[threadIdx.x][threadIdx.y + i]);
}

// bvo[n] = Wo[n,:] . bv + bo[n]  (exact fp32; biases never pass through mma)
__global__ void bvo_kernel(const float* __restrict__ Wo, const float* __restrict__ bv,
                           const float* __restrict__ bo, float* __restrict__ bvo) {
    int n = blockIdx.x * (blockDim.x >> 5) + (threadIdx.x >> 5);
    int lane = threadIdx.x & 31;
    const float* row = Wo + (size_t)n * EDIM;
    float s = 0.f;
    for (int k = lane; k < EDIM; k += 32) s += row[k] * bv[k];
#pragma unroll
    for (int off = 16; off; off >>= 1) s += __shfl_xor_sync(0xFFFFFFFFu, s, off);
    if (lane == 0) bvo[n] = s + bo[n];
}

// ---------------- launch ----------------
static void run_round(const float* src, float* dst, size_t n) {
    int n4 = (int)(n / 4);
    round_tf32_kernel<<<(n4 + 255) / 256, 256>>>(src, dst, n4);
}

extern "C" void kernel_launch(void* const* d_in, const int* in_sizes, int n_in,
                              void* d_out, int out_size)
{
    const float* text  = (const float*)d_in[0];
    const float* audio = (const float*)d_in[1];
    const float* Wt  = (const float*)d_in[2];
    const float* bt  = (const float*)d_in[3];
    const float* Wa  = (const float*)d_in[4];
    const float* ba  = (const float*)d_in[5];
    // d_in[6..9] = Wq,bq,Wk,bk : dead (softmax over length-1 kv axis == 1 -> ctx == v)
    const float* Wv  = (const float*)d_in[10];
    const float* bv  = (const float*)d_in[11];
    const float* Wo  = (const float*)d_in[12];
    const float* bo  = (const float*)d_in[13];
    const float* Wgt = (const float*)d_in[14];
    const float* bgt = (const float*)d_in[15];
    const float* Wga = (const float*)d_in[16];
    const float* bga = (const float*)d_in[17];
    float* out = (float*)d_out;

    float *t, *a, *tctx, *actx, *text_r, *aud_r;
    float *Wt_r, *Wa_r, *Wgt_r, *Wga_r, *Wo_r, *WvT_r, *Wvo, *bvo;
    cudaGetSymbolAddress((void**)&t, g_t);         cudaGetSymbolAddress((void**)&a, g_a);
    cudaGetSymbolAddress((void**)&tctx, g_tctx);   cudaGetSymbolAddress((void**)&actx, g_actx);
    cudaGetSymbolAddress((void**)&text_r, g_text_r);
    cudaGetSymbolAddress((void**)&aud_r, g_aud_r);
    cudaGetSymbolAddress((void**)&Wt_r, g_Wt_r);   cudaGetSymbolAddress((void**)&Wa_r, g_Wa_r);
    cudaGetSymbolAddress((void**)&Wgt_r, g_Wgt_r); cudaGetSymbolAddress((void**)&Wga_r, g_Wga_r);
    cudaGetSymbolAddress((void**)&Wo_r, g_Wo_r);   cudaGetSymbolAddress((void**)&WvT_r, g_WvT_r);
    cudaGetSymbolAddress((void**)&Wvo, g_Wvo);     cudaGetSymbolAddress((void**)&bvo, g_bvo);

    cudaFuncSetAttribute(tc_wmma<false>, cudaFuncAttributeMaxDynamicSharedMemorySize, SMEM_BYTES);
    cudaFuncSetAttribute(tc_wmma<true>,  cudaFuncAttributeMaxDynamicSharedMemorySize, SMEM_BYTES);

    // pre-round all mma operands to exact tf32 values (removes all in-loop cvt)
    run_round(text,  text_r, (size_t)BSZ * TDIM);
    run_round(audio, aud_r,  (size_t)BSZ * EDIM);
    run_round(Wt,  Wt_r,  (size_t)EDIM * TDIM);
    run_round(Wa,  Wa_r,  (size_t)EDIM * EDIM);
    run_round(Wgt, Wgt_r, (size_t)EDIM * 2 * EDIM);
    run_round(Wga, Wga_r, (size_t)EDIM * 2 * EDIM);
    run_round(Wo,  Wo_r,  (size_t)EDIM * EDIM);
    transpose_round1024<<<dim3(32, 32), dim3(32, 8)>>>(Wv, WvT_r);
    bvo_kernel<<<EDIM / 8, 256>>>(Wo, bv, bo, bvo);

    const dim3 blk(128);
    const dim3 gridW(EDIM / 128, EDIM / 128);  // (8, 8)
    const dim3 gridB(EDIM / 128, BSZ / 128);   // (8, 128)

    // Wvo = Wo @ Wv (epilogue emits tf32-rounded values)
    tc_wmma<false><<<gridW, blk, SMEM_BYTES>>>(
        Wo_r, Wo_r, EDIM, WvT_r, EDIM, EDIM, EDIM, nullptr, Wvo, nullptr, nullptr);
    // t = text @ Wt^T + bt ; a = audio @ Wa^T + ba
    tc_wmma<false><<<gridB, blk, SMEM_BYTES>>>(
        text_r, text_r, TDIM, Wt_r, TDIM, TDIM, TDIM, bt, t, nullptr, nullptr);
    tc_wmma<false><<<gridB, blk, SMEM_BYTES>>>(
        aud_r, aud_r, EDIM, Wa_r, EDIM, EDIM, EDIM, ba, a, nullptr, nullptr);
    // contexts: attention collapsed to the fused V-then-O projection
    tc_wmma<false><<<gridB, blk, SMEM_BYTES>>>(
        a, a, EDIM, Wvo, EDIM, EDIM, EDIM, bvo, tctx, nullptr, nullptr);
    tc_wmma<false><<<gridB, blk, SMEM_BYTES>>>(
        t, t, EDIM, Wvo, EDIM, EDIM, EDIM, bvo, actx, nullptr, nullptr);
    // gates: K = 2048, A switches x -> ctx at k = 1024; fused sigmoid blend
    tc_wmma<true><<<gridB, blk, SMEM_BYTES>>>(
        t, tctx, EDIM, Wgt_r, 2 * EDIM, 2 * EDIM, EDIM, bgt, out, t, tctx);
    tc_wmma<true><<<gridB, blk, SMEM_BYTES>>>(
        a, actx, EDIM, Wga_r, 2 * EDIM, 2 * EDIM, EDIM, bga,
        out + (size_t)BSZ * EDIM, a, actx);
}

// round 4
// speedup vs baseline: 4.6348x; 3.8114x over previous
#include <cuda_runtime.h>
#include <cuda_fp16.h>
#include <cstdint>

#define BSZ 16384
#define EDIM 1024
#define TDIM 768

// ---------------- scratch (__device__ globals; allocation is forbidden) ----------------
__device__ float g_t[(size_t)BSZ * EDIM];
__device__ float g_a[(size_t)BSZ * EDIM];
__device__ float g_tctx[(size_t)BSZ * EDIM];
__device__ float g_actx[(size_t)BSZ * EDIM];
__device__ __half g_t_h[(size_t)BSZ * EDIM];
__device__ __half g_a_h[(size_t)BSZ * EDIM];
__device__ __half g_tctx_h[(size_t)BSZ * EDIM];
__device__ __half g_actx_h[(size_t)BSZ * EDIM];
__device__ __half g_text_h[(size_t)BSZ * TDIM];
__device__ __half g_aud_h[(size_t)BSZ * EDIM];
__device__ __half g_Wt_h[(size_t)EDIM * TDIM];
__device__ __half g_Wa_h[(size_t)EDIM * EDIM];
__device__ __half g_Wgt_h[(size_t)EDIM * 2 * EDIM];
__device__ __half g_Wga_h[(size_t)EDIM * 2 * EDIM];
__device__ __half g_Wo_h[(size_t)EDIM * EDIM];
__device__ __half g_WvT_h[(size_t)EDIM * EDIM];
__device__ float g_Wvo[(size_t)EDIM * EDIM];
__device__ __half g_Wvo_h[(size_t)EDIM * EDIM];
__device__ float g_bvo[EDIM];

// ---------------- helpers ----------------
static __device__ __forceinline__ uint32_t s2u(const void* p) {
    uint32_t a;
    asm("{ .reg .u64 t; cvta.to.shared.u64 t, %1; cvt.u32.u64 %0, t; }" : "=r"(a) : "l"(p));
    return a;
}
static __device__ __forceinline__ void cpa16(uint32_t d, const void* s) {
    asm volatile("cp.async.cg.shared.global [%0], [%1], 16;" :: "r"(d), "l"(s));
}
static __device__ __forceinline__ void cpa_commit() { asm volatile("cp.async.commit_group;"); }
static __device__ __forceinline__ void ldsm4(uint32_t* r, uint32_t addr) {
    asm volatile("ldmatrix.sync.aligned.m8n8.x4.shared.b16 {%0,%1,%2,%3}, [%4];"
                 : "=r"(r[0]), "=r"(r[1]), "=r"(r[2]), "=r"(r[3]) : "r"(addr));
}
static __device__ __forceinline__ void mma16816(float* c, const uint32_t* a, uint32_t b0, uint32_t b1) {
    asm volatile(
        "mma.sync.aligned.m16n8k16.row.col.f32.f16.f16.f32 "
        "{%0,%1,%2,%3}, {%4,%5,%6,%7}, {%8,%9}, {%0,%1,%2,%3};"
        : "+f"(c[0]), "+f"(c[1]), "+f"(c[2]), "+f"(c[3])
        : "r"(a[0]), "r"(a[1]), "r"(a[2]), "r"(a[3]), "r"(b0), "r"(b1));
}

// ---------------- SMEM layout ----------------
// fp16 K-tile: 32 halves/row = 64 B, padded to 80 B (20-word stride: 8 rows hit
// 8 distinct banks -> conflict-free ldmatrix). A buf 128*80 = 10240 B, B same.
// Stage = 20480 B, 3 stages = 61440 B. Epilogue reuses smem as 128 x 132 f32 = 67584 B.
#define STAGE_BYTES 20480
#define SMEM_BYTES 67584

struct GArgs {
    const __half* A0; const __half* A1; const __half* W;
    const float* bias; float* C; __half* Ch;
    const float* X; const float* Xc;
    int lda, ldw, K, Ksplit;
};

// C[row, col] = sum_k A[row, k] * W[col, k] (+ bias[col]); A switches A0->A1 at
// k = Ksplit (concat-free gate). GATE: fused sigmoid blend. !GATE: emits C (f32) + Ch (f16).
template <bool GATE>
__global__ __launch_bounds__(256) void hgemm(GArgs ga, GArgs gb)
{
    const GArgs g = (blockIdx.z == 0) ? ga : gb;
    extern __shared__ __align__(16) char smem[];
    const uint32_t sb = s2u(smem);
    const int tid  = threadIdx.x;
    const int warp = tid >> 5;
    const int lane = tid & 31;
    const int bm = blockIdx.y * 128;
    const int bn = blockIdx.x * 128;
    const int wm = (warp & 1) * 64;    // warp tile 64x32, warp grid 2x4
    const int wn = (warp >> 1) * 32;
    const int T = g.K / 32;

    // cp.async mapping: thread -> row tid/2, 32B chunk (tid&1)
    const int rowL = tid >> 1;
    const int cL = (tid & 1) * 2;

    auto issue = [&](int ti, int s) {
        const int k0 = ti * 32;
        const __half* Ap; int kk;
        if (k0 < g.Ksplit) { Ap = g.A0; kk = k0; }
        else               { Ap = g.A1; kk = k0 - g.Ksplit; }
        const __half* srcA = Ap + (size_t)(bm + rowL) * g.lda + kk + cL * 8;
        const uint32_t dA = sb + s * STAGE_BYTES + rowL * 80 + cL * 16;
        cpa16(dA, srcA); cpa16(dA + 16, srcA + 8);
        const __half* srcB = g.W + (size_t)(bn + rowL) * g.ldw + k0 + cL * 8;
        const uint32_t dB = sb + s * STAGE_BYTES + 10240 + rowL * 80 + cL * 16;
        cpa16(dB, srcB); cpa16(dB + 16, srcB + 8);
        cpa_commit();
    };

    issue(0, 0);
    issue(1, 1);

    // ldmatrix per-thread base offsets
    const uint32_t aoff = (uint32_t)(wm + (lane & 15)) * 80 + (lane >> 4) * 16;
    const uint32_t boff = (uint32_t)(wn + ((lane >> 4) & 1) * 8 + (lane & 7)) * 80 +
                          ((lane >> 3) & 1) * 16;

    float acc[4][4][4];
#pragma unroll
    for (int i = 0; i < 4; i++)
#pragma unroll
        for (int j = 0; j < 4; j++)
#pragma unroll
            for (int q = 0; q < 4; q++) acc[i][j][q] = 0.f;

    for (int ti = 0; ti < T; ti++) {
        const int s = ti % 3;
        if (ti < T - 1) asm volatile("cp.async.wait_group 1;");
        else            asm volatile("cp.async.wait_group 0;");
        __syncthreads();
        if (ti + 2 < T) issue(ti + 2, (ti + 2) % 3);

        const uint32_t sA = sb + s * STAGE_BYTES;
        const uint32_t sB = sA + 10240;
#pragma unroll
        for (int ks = 0; ks < 2; ks++) {
            uint32_t ar[4][4], br[2][4];
#pragma unroll
            for (int mi = 0; mi < 4; mi++)
                ldsm4(ar[mi], sA + aoff + mi * (16 * 80) + ks * 32);
#pragma unroll
            for (int nj = 0; nj < 2; nj++)
                ldsm4(br[nj], sB + boff + nj * (16 * 80) + ks * 32);
#pragma unroll
            for (int mi = 0; mi < 4; mi++)
#pragma unroll
                for (int ni = 0; ni < 4; ni++)
                    mma16816(acc[mi][ni], ar[mi],
                             br[ni >> 1][(ni & 1) * 2], br[ni >> 1][(ni & 1) * 2 + 1]);
        }
    }

    // ---- epilogue: accumulators -> smem (f32), then fused row pass
    __syncthreads();
    float* Cs = (float*)smem;
#pragma unroll
    for (int mi = 0; mi < 4; mi++)
#pragma unroll
        for (int ni = 0; ni < 4; ni++) {
            const int r0 = wm + mi * 16 + (lane >> 2);
            const int c0 = wn + ni * 8 + (lane & 3) * 2;
            Cs[r0 * 132 + c0]           = acc[mi][ni][0];
            Cs[r0 * 132 + c0 + 1]       = acc[mi][ni][1];
            Cs[(r0 + 8) * 132 + c0]     = acc[mi][ni][2];
            Cs[(r0 + 8) * 132 + c0 + 1] = acc[mi][ni][3];
        }
    __syncthreads();

    {
        const int r  = tid >> 1;
        const int ch = (tid & 1) * 64;
        const size_t rowoff = (size_t)(bm + r) * EDIM + bn + ch;
        const float* csrow = Cs + r * 132 + ch;
#pragma unroll 4
        for (int q = 0; q < 16; q++) {
            float4 v = *(const float4*)(csrow + q * 4);
            if (g.bias) {
                float4 bb = *(const float4*)(g.bias + bn + ch + q * 4);
                v.x += bb.x; v.y += bb.y; v.z += bb.z; v.w += bb.w;
            }
            if (GATE) {
                float4 xv = *(const float4*)(g.X + rowoff + q * 4);
                float4 cv = *(const float4*)(g.Xc + rowoff + q * 4);
                float g0 = 1.f / (1.f + __expf(-v.x));
                float g1 = 1.f / (1.f + __expf(-v.y));
                float g2 = 1.f / (1.f + __expf(-v.z));
                float g3 = 1.f / (1.f + __expf(-v.w));
                v.x = g0 * xv.x + (1.f - g0) * cv.x;
                v.y = g1 * xv.y + (1.f - g1) * cv.y;
                v.z = g2 * xv.z + (1.f - g2) * cv.z;
                v.w = g3 * xv.w + (1.f - g3) * cv.w;
                *(float4*)(g.C + rowoff + q * 4) = v;
            } else {
                *(float4*)(g.C + rowoff + q * 4) = v;
                __half2 h0 = __floats2half2_rn(v.x, v.y);
                __half2 h1 = __floats2half2_rn(v.z, v.w);
                uint2 u;
                u.x = *(uint32_t*)&h0; u.y = *(uint32_t*)&h1;
                *(uint2*)(g.Ch + rowoff + q * 4) = u;
            }
        }
    }
}

// ---------------- small helper kernels ----------------
__global__ void cvt_kernel(const float* __restrict__ in, __half* __restrict__ out, int n4) {
    int i = blockIdx.x * blockDim.x + threadIdx.x;
    if (i >= n4) return;
    float4 v = ((const float4*)in)[i];
    __half2 h0 = __floats2half2_rn(v.x, v.y);
    __half2 h1 = __floats2half2_rn(v.z, v.w);
    uint2 u; u.x = *(uint32_t*)&h0; u.y = *(uint32_t*)&h1;
    ((uint2*)out)[i] = u;
}

// out[k][j] = half(in[j][k]) for 1024x1024
__global__ void transpose_cvt1024(const float* __restrict__ in, __half* __restrict__ out) {
    __shared__ float tile[32][33];
    int x = blockIdx.x * 32 + threadIdx.x;
    int y = blockIdx.y * 32 + threadIdx.y;
#pragma unroll
    for (int i = 0; i < 32; i += 8)
        tile[threadIdx.y + i][threadIdx.x] = in[(size_t)(y + i) * EDIM + x];
    __syncthreads();
    x = blockIdx.y * 32 + threadIdx.x;
    y = blockIdx.x * 32 + threadIdx.y;
#pragma unroll
    for (int i = 0; i < 32; i += 8)
        out[(size_t)(y + i) * EDIM + x] = __float2half_rn(tile[threadIdx.x][threadIdx.y + i]);
}

// bvo[n] = Wo[n,:] . bv + bo[n]  (exact fp32)
__global__ void bvo_kernel(const float* __restrict__ Wo, const float* __restrict__ bv,
                           const float* __restrict__ bo, float* __restrict__ bvo) {
    int n = blockIdx.x * (blockDim.x >> 5) + (threadIdx.x >> 5);
    int lane = threadIdx.x & 31;
    const float* row = Wo + (size_t)n * EDIM;
    float s = 0.f;
    for (int k = lane; k < EDIM; k += 32) s += row[k] * bv[k];
#pragma unroll
    for (int off = 16; off; off >>= 1) s += __shfl_xor_sync(0xFFFFFFFFu, s, off);
    if (lane == 0) bvo[n] = s + bo[n];
}

// ---------------- launch ----------------
static void run_cvt(const float* src, __half* dst, size_t n) {
    int n4 = (int)(n / 4);
    cvt_kernel<<<(n4 + 255) / 256, 256>>>(src, dst, n4);
}

extern "C" void kernel_launch(void* const* d_in, const int* in_sizes, int n_in,
                              void* d_out, int out_size)
{
    const float* text  = (const float*)d_in[0];
    const float* audio = (const float*)d_in[1];
    const float* Wt  = (const float*)d_in[2];
    const float* bt  = (const float*)d_in[3];
    const float* Wa  = (const float*)d_in[4];
    const float* ba  = (const float*)d_in[5];
    // d_in[6..9] = Wq,bq,Wk,bk : dead (softmax over length-1 kv axis == 1 -> ctx == v)
    const float* Wv  = (const float*)d_in[10];
    const float* bv  = (const float*)d_in[11];
    const float* Wo  = (const float*)d_in[12];
    const float* bo  = (const float*)d_in[13];
    const float* Wgt = (const float*)d_in[14];
    const float* bgt = (const float*)d_in[15];
    const float* Wga = (const float*)d_in[16];
    const float* bga = (const float*)d_in[17];
    float* out = (float*)d_out;

    float *t, *a, *tctx, *actx, *Wvo, *bvo;
    __half *t_h, *a_h, *tctx_h, *actx_h, *text_h, *aud_h;
    __half *Wt_h, *Wa_h, *Wgt_h, *Wga_h, *Wo_h, *WvT_h, *Wvo_h;
    cudaGetSymbolAddress((void**)&t, g_t);           cudaGetSymbolAddress((void**)&a, g_a);
    cudaGetSymbolAddress((void**)&tctx, g_tctx);     cudaGetSymbolAddress((void**)&actx, g_actx);
    cudaGetSymbolAddress((void**)&t_h, g_t_h);       cudaGetSymbolAddress((void**)&a_h, g_a_h);
    cudaGetSymbolAddress((void**)&tctx_h, g_tctx_h); cudaGetSymbolAddress((void**)&actx_h, g_actx_h);
    cudaGetSymbolAddress((void**)&text_h, g_text_h); cudaGetSymbolAddress((void**)&aud_h, g_aud_h);
    cudaGetSymbolAddress((void**)&Wt_h, g_Wt_h);     cudaGetSymbolAddress((void**)&Wa_h, g_Wa_h);
    cudaGetSymbolAddress((void**)&Wgt_h, g_Wgt_h);   cudaGetSymbolAddress((void**)&Wga_h, g_Wga_h);
    cudaGetSymbolAddress((void**)&Wo_h, g_Wo_h);     cudaGetSymbolAddress((void**)&WvT_h, g_WvT_h);
    cudaGetSymbolAddress((void**)&Wvo, g_Wvo);       cudaGetSymbolAddress((void**)&Wvo_h, g_Wvo_h);
    cudaGetSymbolAddress((void**)&bvo, g_bvo);

    cudaFuncSetAttribute(hgemm<false>, cudaFuncAttributeMaxDynamicSharedMemorySize, SMEM_BYTES);
    cudaFuncSetAttribute(hgemm<true>,  cudaFuncAttributeMaxDynamicSharedMemorySize, SMEM_BYTES);

    // fp16 operand prep
    run_cvt(text,  text_h, (size_t)BSZ * TDIM);
    run_cvt(audio, aud_h,  (size_t)BSZ * EDIM);
    run_cvt(Wt,  Wt_h,  (size_t)EDIM * TDIM);
    run_cvt(Wa,  Wa_h,  (size_t)EDIM * EDIM);
    run_cvt(Wgt, Wgt_h, (size_t)EDIM * 2 * EDIM);
    run_cvt(Wga, Wga_h, (size_t)EDIM * 2 * EDIM);
    run_cvt(Wo,  Wo_h,  (size_t)EDIM * EDIM);
    transpose_cvt1024<<<dim3(32, 32), dim3(32, 8)>>>(Wv, WvT_h);
    bvo_kernel<<<EDIM / 8, 256>>>(Wo, bv, bo, bvo);

    const dim3 blk(256);

    // Wvo = Wo @ Wv (emits f32 + f16)
    {
        GArgs gw = { Wo_h, Wo_h, WvT_h, nullptr, Wvo, Wvo_h, nullptr, nullptr,
                     EDIM, EDIM, EDIM, EDIM };
        hgemm<false><<<dim3(8, 8, 1), blk, SMEM_BYTES>>>(gw, gw);
    }
    // projections (batched via z): t = text@Wt^T + bt ; a = audio@Wa^T + ba
    {
        GArgs gt = { text_h, text_h, Wt_h, bt, t, t_h, nullptr, nullptr,
                     TDIM, TDIM, TDIM, TDIM };
        GArgs gaa = { aud_h, aud_h, Wa_h, ba, a, a_h, nullptr, nullptr,
                      EDIM, EDIM, EDIM, EDIM };
        hgemm<false><<<dim3(8, 128, 2), blk, SMEM_BYTES>>>(gt, gaa);
    }
    // contexts (attention collapsed to V-then-O): tctx = a@Wvo^T + bvo ; actx = t@Wvo^T + bvo
    {
        GArgs g0 = { a_h, a_h, Wvo_h, bvo, tctx, tctx_h, nullptr, nullptr,
                     EDIM, EDIM, EDIM, EDIM };
        GArgs g1 = { t_h, t_h, Wvo_h, bvo, actx, actx_h, nullptr, nullptr,
                     EDIM, EDIM, EDIM, EDIM };
        hgemm<false><<<dim3(8, 128, 2), blk, SMEM_BYTES>>>(g0, g1);
    }
    // gates: K = 2048, A switches x -> ctx at k = 1024; fused sigmoid blend
    {
        GArgs g0 = { t_h, tctx_h, Wgt_h, bgt, out, nullptr, t, tctx,
                     EDIM, 2 * EDIM, 2 * EDIM, EDIM };
        GArgs g1 = { a_h, actx_h, Wga_h, bga, out + (size_t)BSZ * EDIM, nullptr, a, actx,
                     EDIM, 2 * EDIM, 2 * EDIM, EDIM };
        hgemm<true><<<dim3(8, 128, 2), blk, SMEM_BYTES>>>(g0, g1);
    }
}